// round 10
// baseline (speedup 1.0000x reference)
#include <cuda_runtime.h>
#include <cuda_fp16.h>
#include <math.h>
#include <stdint.h>

#define TOK    16384
#define DMODEL 2048
#define EEXP   8
#define NKAN   2
#define DD     256
#define HH     1024
#define MT     64
#define NTHR   256
#define WSC    64.0f
#define WSCI   (1.0f / 64.0f)

// ---------------- global scratch (fp16; weights pre-scaled x64) ----------------
__device__ __align__(16) __half g_x[(size_t)TOK * DMODEL];
__device__ __align__(16) __half g_w1h[(size_t)EEXP * HH * DD];   // [e][h][d]
__device__ __align__(16) __half g_w2mh[(size_t)6 * DD * HH];     // [m][o][h]
__device__ __align__(16) __half g_w2kh[(size_t)6 * DD * HH];     // [e*3+p-1][o][h]
__device__ float g_c0[NKAN * DD];

// ---------------- smem layout (bytes) — 113664 B: 2 CTAs/SM ----------------
#define PX     528
#define PW2    144
#define SM_X   0                      // 64 x 528 = 33792
#define SM_W1H 33792                  // 64 x 528 = 33792
#define SM_W2H 67584                  // 2 halves x 128 x 144 = 36864
#define SM_A   104448                 // 64 x 144 = 9216
#define SM_TOTAL 113664

// ---------------- PTX helpers ----------------
__device__ __forceinline__ uint32_t smem_u32(const void* p) {
    uint32_t a;
    asm("{ .reg .u64 t; cvta.to.shared.u64 t, %1; cvt.u32.u64 %0, t; }" : "=r"(a) : "l"(p));
    return a;
}
__device__ __forceinline__ void cp16(uint32_t d, const void* s) {
    asm volatile("cp.async.cg.shared.global [%0], [%1], 16;" :: "r"(d), "l"(s));
}
#define CP_COMMIT() asm volatile("cp.async.commit_group;" ::: "memory")
#define CP_WAIT(N)  asm volatile("cp.async.wait_group %0;" :: "n"(N) : "memory")

__device__ __forceinline__ void ldsm4(uint32_t addr, uint32_t* r) {
    asm volatile("ldmatrix.sync.aligned.m8n8.x4.shared.b16 {%0,%1,%2,%3}, [%4];"
                 : "=r"(r[0]), "=r"(r[1]), "=r"(r[2]), "=r"(r[3]) : "r"(addr));
}
__device__ __forceinline__ void mma16816(float c[4], const uint32_t a[4],
                                         uint32_t b0, uint32_t b1) {
    asm volatile("mma.sync.aligned.m16n8k16.row.col.f32.f16.f16.f32 "
                 "{%0,%1,%2,%3}, {%4,%5,%6,%7}, {%8,%9}, {%0,%1,%2,%3};"
                 : "+f"(c[0]), "+f"(c[1]), "+f"(c[2]), "+f"(c[3])
                 : "r"(a[0]), "r"(a[1]), "r"(a[2]), "r"(a[3]), "r"(b0), "r"(b1));
}
__device__ __forceinline__ float fast_tanh(float x) {
    float e = __expf(2.0f * x);
    return 1.0f - __fdividef(2.0f, e + 1.0f);
}
__device__ __forceinline__ float gelu_tanh(float v) {
    float u = 0.7978845608028654f * (v + 0.044715f * v * v * v);
    return 0.5f * v * (1.0f + fast_tanh(u));
}

// ---------------- staging (cp.async, 256 threads) ----------------
__device__ __forceinline__ void stage64(uint32_t dst, const __half* src,
                                        int spitch, int tid) {
    const char* s = (const char*)src;
    #pragma unroll
    for (int i = 0; i < 8; ++i) {
        int idx = i * NTHR + tid, r = idx >> 5, c = idx & 31;   // 64 rows x 32
        cp16(dst + r * PX + c * 16, s + (size_t)r * spitch + c * 16);
    }
}
__device__ __forceinline__ void stage128(uint32_t dst, const __half* src, int tid) {
    const char* s = (const char*)src;   // pitch 2048 B
    #pragma unroll
    for (int i = 0; i < 4; ++i) {
        int idx = i * NTHR + tid, r = idx >> 3, c = idx & 7;    // 128 rows x 8
        cp16(dst + r * PW2 + c * 16, s + (size_t)r * 2048 + c * 16);
    }
}
__device__ __forceinline__ void stage_w2(uint32_t sb, int j, int s, bool isKan,
                                         int e, int m, int tid) {
    int half = s & 1;
    const __half* sh;
    if (isKan)
        sh = g_w2kh + ((size_t)(e * 3 + (s >> 1)) * DD + half * 128) * HH + j * 64;
    else
        sh = g_w2mh + ((size_t)m * DD + half * 128) * HH + j * 64;
    stage128(sb + SM_W2H + half * 18432, sh, tid);
}

// ---------------- prologue kernels ----------------
__global__ void c0_kernel(const float* __restrict__ kpw, const float* __restrict__ kb) {
    int e = blockIdx.x, o = threadIdx.x;
    const float* w0 = kpw + (size_t)e * 4 * HH * DD;
    float s = kb[e * DD + o];
    for (int h = 0; h < HH; ++h) s += w0[(size_t)h * DD + o];
    g_c0[e * DD + o] = s;
}
__global__ void xhalf(const float* __restrict__ x) {
    size_t i = ((size_t)blockIdx.x * 256 + threadIdx.x) * 4;
    float4 v = *(const float4*)(x + i);
    *(__half2*)(g_x + i)     = __floats2half2_rn(v.x, v.y);
    *(__half2*)(g_x + i + 2) = __floats2half2_rn(v.z, v.w);
}
// transpose (+WSC scale)
__device__ __forceinline__ void tconv_body(const float* src, __half* dh, int K, int N) {
    __shared__ float ts[32][33];
    int k0 = blockIdx.x * 32, n0 = blockIdx.y * 32;
    int tx = threadIdx.x, ty = threadIdx.y;
    #pragma unroll
    for (int i = 0; i < 4; ++i)
        ts[ty + 8 * i][tx] = src[(size_t)(k0 + ty + 8 * i) * N + n0 + tx];
    __syncthreads();
    #pragma unroll
    for (int i = 0; i < 4; ++i) {
        int n = n0 + ty + 8 * i, k = k0 + tx;
        dh[(size_t)n * K + k] = __float2half(ts[tx][ty + 8 * i] * WSC);
    }
}
__global__ void tconv_w1(const float* __restrict__ klw, const float* __restrict__ mw1) {
    int e = blockIdx.z;
    const float* src = (e < NKAN) ? klw + (size_t)e * DD * HH
                                  : mw1 + (size_t)(e - NKAN) * DD * HH;
    tconv_body(src, g_w1h + (size_t)e * HH * DD, DD, HH);
}
__global__ void tconv_w2m(const float* __restrict__ mw2) {
    int z = blockIdx.z;
    tconv_body(mw2 + (size_t)z * HH * DD, g_w2mh + (size_t)z * DD * HH, HH, DD);
}
__global__ void tconv_w2k(const float* __restrict__ kpw) {
    int z = blockIdx.z, e = z / 3, p = z % 3 + 1;
    tconv_body(kpw + (size_t)(e * 4 + p) * HH * DD, g_w2kh + (size_t)z * DD * HH, HH, DD);
}

// ---------------- main fused kernel: 64-token tile, 8 warps, 2 CTAs/SM ------
__global__ void __launch_bounds__(NTHR, 2)
ffn_mma(const float* __restrict__ mlp_b1, const float* __restrict__ mlp_b2,
        float* __restrict__ out) {
    extern __shared__ __align__(16) char smc[];
    const uint32_t sb = smem_u32(smc);
    const int tid = threadIdx.x, wid = tid >> 5, lane = tid & 31;
    const int e = blockIdx.y, tile = blockIdx.x, t0 = tile * MT;
    const bool isKan = (e < NKAN);
    const int m = e - NKAN;
    const int npoly = isKan ? 3 : 1;
    const int ns = 2 * npoly;
    const int wm = wid & 1, wn = wid >> 1;   // 2 x 4 warp grid

    {
        stage64(sb + SM_X, g_x + (size_t)t0 * DMODEL + e * DD, DMODEL * 2, tid);
        CP_COMMIT();
        stage64(sb + SM_W1H, g_w1h + (size_t)e * HH * DD, 512, tid);
        CP_COMMIT();
        stage_w2(sb, 0, 0, isKan, e, m, tid); CP_COMMIT();
        stage_w2(sb, 0, 1, isKan, e, m, tid); CP_COMMIT();
    }

    float acc[2][2][4][4];
    #pragma unroll
    for (int a = 0; a < 2; ++a)
        #pragma unroll
        for (int b = 0; b < 2; ++b)
            #pragma unroll
            for (int c = 0; c < 4; ++c)
                #pragma unroll
                for (int d = 0; d < 4; ++d) acc[a][b][c][d] = 0.f;

    const int lr = (lane & 7) + 8 * ((lane >> 3) & 1);
    const int lk = (lane >> 4) * 16;
    const uint32_t aX  = sb + SM_X   + (32 * wm + lr) * PX  + lk;
    const uint32_t aW1 = sb + SM_W1H + (16 * wn + lr) * PX  + lk;
    const uint32_t aA  = sb + SM_A   + (32 * wm + lr) * PW2 + lk;
    const uint32_t aW2 = sb + SM_W2H + (32 * wn + lr) * PW2 + lk;

    for (int j = 0; j < 16; ++j) {
        if (isKan && j) { CP_WAIT(6); } else { CP_WAIT(2); }
        __syncthreads();

        // ---- GEMM1: A(fp16)[64x256] x W1h[256x64], warp tile 32x16 ----
        float c1[2][2][4];
        #pragma unroll
        for (int a = 0; a < 2; ++a)
            #pragma unroll
            for (int b = 0; b < 2; ++b)
                #pragma unroll
                for (int c = 0; c < 4; ++c) c1[a][b][c] = 0.f;

        #pragma unroll
        for (int kk = 0; kk < 16; ++kk) {
            uint32_t fa[8], fb[4];
            ldsm4(aX + kk * 32, fa);
            ldsm4(aX + 16 * PX + kk * 32, fa + 4);
            ldsm4(aW1 + kk * 32, fb);
            mma16816(c1[0][0], fa + 0, fb[0], fb[2]);
            mma16816(c1[0][1], fa + 0, fb[1], fb[3]);
            mma16816(c1[1][0], fa + 4, fb[0], fb[2]);
            mma16816(c1[1][1], fa + 4, fb[1], fb[3]);
        }
        __syncthreads();
        if (j < 15) {
            stage64(sb + SM_W1H, g_w1h + ((size_t)e * HH + (j + 1) * 64) * DD, 512, tid);
            CP_COMMIT();
        }

        // ---- activation, in place (undo x64 weight scale) ----
        if (isKan) {
            #pragma unroll
            for (int a = 0; a < 2; ++a)
                #pragma unroll
                for (int b = 0; b < 2; ++b)
                    #pragma unroll
                    for (int c = 0; c < 4; ++c)
                        c1[a][b][c] = fast_tanh(c1[a][b][c] * WSCI);
        } else {
            #pragma unroll
            for (int nt = 0; nt < 2; ++nt) {
                int col = j * 64 + 16 * wn + 8 * nt + 2 * (lane & 3);
                float2 bv = *(const float2*)(mlp_b1 + (size_t)m * HH + col);
                #pragma unroll
                for (int a = 0; a < 2; ++a) {
                    c1[a][nt][0] = gelu_tanh(c1[a][nt][0] * WSCI + bv.x);
                    c1[a][nt][1] = gelu_tanh(c1[a][nt][1] * WSCI + bv.y);
                    c1[a][nt][2] = gelu_tanh(c1[a][nt][2] * WSCI + bv.x);
                    c1[a][nt][3] = gelu_tanh(c1[a][nt][3] * WSCI + bv.y);
                }
            }
        }

        for (int p = 1; p <= npoly; ++p) {
            #pragma unroll
            for (int a = 0; a < 2; ++a)
                #pragma unroll
                for (int nt = 0; nt < 2; ++nt) {
                    float v[4];
                    #pragma unroll
                    for (int c = 0; c < 4; ++c) {
                        float t = c1[a][nt][c];
                        v[c] = (p == 1) ? t
                             : (p == 2) ? fmaf(2.f * t, t, -1.f)
                                        : t * fmaf(4.f * t, t, -3.f);
                    }
                    int rowb = 32 * wm + 16 * a + (lane >> 2);
                    int colb = (16 * wn + 8 * nt + 2 * (lane & 3)) * 2;
                    *(__half2*)(smc + SM_A + rowb * PW2 + colb) = __floats2half2_rn(v[0], v[1]);
                    *(__half2*)(smc + SM_A + (rowb + 8) * PW2 + colb) = __floats2half2_rn(v[2], v[3]);
                }

            #pragma unroll
            for (int sub = 0; sub < 2; ++sub) {
                int s = (p - 1) * 2 + sub;
                if (s < 2) { CP_WAIT(2); } else { CP_WAIT(1); }
                __syncthreads();
                const uint32_t w2b = aW2 + sub * 18432;
                #pragma unroll
                for (int kk = 0; kk < 4; ++kk) {
                    uint32_t Fa[8], Fb[8];
                    ldsm4(aA + kk * 32, Fa);
                    ldsm4(aA + 16 * PW2 + kk * 32, Fa + 4);
                    ldsm4(w2b + kk * 32, Fb);
                    ldsm4(w2b + 16 * PW2 + kk * 32, Fb + 4);
                    #pragma unroll
                    for (int a = 0; a < 2; ++a)
                        #pragma unroll
                        for (int nt = 0; nt < 4; ++nt)
                            mma16816(acc[sub][a][nt], Fa + a * 4,
                                     Fb[4 * (nt >> 1) + (nt & 1)],
                                     Fb[4 * (nt >> 1) + (nt & 1) + 2]);
                }
                __syncthreads();
                int ss = s + 2;
                if (ss < ns) { stage_w2(sb, j, ss, isKan, e, m, tid); CP_COMMIT(); }
                else if (j < 15) { stage_w2(sb, j + 1, ss - ns, isKan, e, m, tid); CP_COMMIT(); }
            }
        }
    }

    // ---- epilogue: out = acc/64 + bias ----
    const float* bp = isKan ? (g_c0 + e * DD) : (mlp_b2 + (size_t)m * DD);
    #pragma unroll
    for (int sub = 0; sub < 2; ++sub)
        #pragma unroll
        for (int a = 0; a < 2; ++a)
            #pragma unroll
            for (int nt = 0; nt < 4; ++nt) {
                int row = t0 + 32 * wm + 16 * a + (lane >> 2);
                int col = sub * 128 + 32 * wn + 8 * nt + 2 * (lane & 3);
                float2 v0, v1;
                v0.x = acc[sub][a][nt][0] * WSCI + bp[col];
                v0.y = acc[sub][a][nt][1] * WSCI + bp[col + 1];
                v1.x = acc[sub][a][nt][2] * WSCI + bp[col];
                v1.y = acc[sub][a][nt][3] * WSCI + bp[col + 1];
                *(float2*)(out + (size_t)row * DMODEL + e * DD + col) = v0;
                *(float2*)(out + (size_t)(row + 8) * DMODEL + e * DD + col) = v1;
            }
}

extern "C" void kernel_launch(void* const* d_in, const int* in_sizes, int n_in,
                              void* d_out, int out_size) {
    const float* x   = (const float*)d_in[0];
    const float* klw = (const float*)d_in[1];
    const float* kpw = (const float*)d_in[2];
    const float* kb  = (const float*)d_in[3];
    const float* w1  = (const float*)d_in[4];
    const float* b1  = (const float*)d_in[5];
    const float* w2  = (const float*)d_in[6];
    const float* b2  = (const float*)d_in[7];
    float* out = (float*)d_out;

    cudaFuncSetAttribute(ffn_mma, cudaFuncAttributeMaxDynamicSharedMemorySize, SM_TOTAL);

    c0_kernel<<<NKAN, DD>>>(kpw, kb);
    xhalf<<<TOK * DMODEL / 1024, 256>>>(x);
    tconv_w1<<<dim3(DD / 32, HH / 32, EEXP), dim3(32, 8)>>>(klw, w1);
    tconv_w2m<<<dim3(HH / 32, DD / 32, 6), dim3(32, 8)>>>(w2);
    tconv_w2k<<<dim3(HH / 32, DD / 32, 6), dim3(32, 8)>>>(kpw);
    ffn_mma<<<dim3(TOK / MT, EEXP), NTHR, SM_TOTAL>>>(b1, b2, out);
}